// round 1
// baseline (speedup 1.0000x reference)
#include <cuda_runtime.h>
#include <math.h>

#define BQ   2048     // total agents (B)
#define HD   64
#define ATTD 1024
#define PADK 80       // 68 padded to multiple of 16

// ---------------- device scratch (static, no allocations) ----------------
__device__ float g_dec[BQ * ATTD];                 // dec_a = h@W_dec + b_dec
__device__ float g_encR[(size_t)BQ * 64 * HD];     // compacted nonzero enc rows
__device__ int   g_rowb[BQ * 64];                  // anchor id per compact row
__device__ int   g_base[BQ];                       // compact base per anchor
__device__ int   g_nnz[BQ];                        // nonzero cell count per anchor
__device__ float g_scoreR[BQ * 64];                // score per compact row
__device__ int   g_R;                              // total compact rows
__device__ float g_ctxemb[BQ * PADK];              // [ctx(64) | emb(4) | zeros(12)]
__device__ float g_WoutP[PADK * ATTD];             // W_out padded 68->80 rows
__device__ float g_out[BQ * ATTD];
__device__ float g_x[BQ * ATTD];
__device__ float g_bna[ATTD];                      // gamma*rstd
__device__ float g_bnb[ATTD];                      // beta - mu*gamma*rstd

__global__ void k_init() { g_R = 0; }

// ---------------- social pooling + compaction (block per anchor) ----------------
__global__ void k_pool(const float* __restrict__ h, const float* __restrict__ end_pos) {
    int b = blockIdx.x;        // anchor global id
    int s = b >> 6;            // sequence
    int i = b & 63;            // anchor within sequence
    int d = threadIdx.x;       // 64 threads = one per hidden dim

    __shared__ float hsh[64 * 64];
    __shared__ float acc[64 * 64];
    __shared__ float px[64], py[64];
    __shared__ int   cellj[64];
    __shared__ int   nz[64];
    __shared__ int   slot_cell[64];
    __shared__ int   sh_base, sh_n;

    for (int t = d; t < 4096; t += 64) { hsh[t] = h[s * 4096 + t]; acc[t] = 0.f; }
    px[d] = end_pos[(s * 64 + d) * 2 + 0];
    py[d] = end_pos[(s * 64 + d) * 2 + 1];
    nz[d] = 0;
    __syncthreads();

    {
        float ax = px[i], ay = py[i];
        float tlx = ax - 1.0f, tly = ay + 1.0f;
        float brx = ax + 1.0f, bry = ay - 1.0f;
        float ox = px[d], oy = py[d];
        bool oob = (ox >= brx) || (ox <= tlx) || (oy >= tly) || (oy <= bry) || (d == i);
        int c = -1;
        if (!oob) {
            float cx = floorf((ox - tlx) / 2.0f * 8.0f);
            float cy = floorf((tly - oy) / 2.0f * 8.0f);
            c = (int)(cx + cy * 8.0f);
        }
        cellj[d] = c;
    }
    __syncthreads();

    for (int j = 0; j < 64; j++) {
        int c = cellj[j];
        if (c >= 0) {
            acc[c * 64 + d] += hsh[j * 64 + d];
            nz[c] = 1;
        }
    }
    __syncthreads();

    if (d == 0) {
        int n = 0;
        for (int c = 0; c < 64; c++) if (nz[c]) slot_cell[n++] = c;
        int base = atomicAdd(&g_R, n);
        sh_base = base; sh_n = n;
        g_base[b] = base; g_nnz[b] = n;
    }
    __syncthreads();

    int base = sh_base, n = sh_n;
    for (int t = 0; t < n; t++) {
        int c = slot_cell[t];
        g_encR[(size_t)(base + t) * 64 + d] = acc[c * 64 + d];
        if (d == 0) g_rowb[base + t] = b;
    }
}

// ---------------- generic fp32 SGEMM: C = act(A[M,K]@B[K,N] + bias) ----------------
// M, N multiples of 64; K multiple of 16. 256 threads, 64x64 tile, 4x4 micro.
template<int RELU>
__global__ void k_sgemm(const float* __restrict__ A, const float* __restrict__ B,
                        const float* __restrict__ bias, float* __restrict__ C,
                        int N, int K) {
    __shared__ float As[16][64];
    __shared__ float Bs[16][64];
    int tid = threadIdx.x;
    int m0 = blockIdx.y * 64;
    int n0 = blockIdx.x * 64;
    int tr = tid >> 4, tc = tid & 15;
    int lar = tid >> 2;          // A tile row
    int lac = (tid & 3) << 2;    // A tile k (float4)
    int lbr = tid >> 4;          // B tile k
    int lbc = (tid & 15) << 2;   // B tile col (float4)

    float acc[4][4] = {};
    for (int k0 = 0; k0 < K; k0 += 16) {
        float4 av = *(const float4*)(A + (size_t)(m0 + lar) * K + k0 + lac);
        As[lac + 0][lar] = av.x; As[lac + 1][lar] = av.y;
        As[lac + 2][lar] = av.z; As[lac + 3][lar] = av.w;
        *(float4*)&Bs[lbr][lbc] = *(const float4*)(B + (size_t)(k0 + lbr) * N + n0 + lbc);
        __syncthreads();
#pragma unroll
        for (int k = 0; k < 16; k++) {
            float4 a  = *(float4*)&As[k][tr * 4];
            float4 bv = *(float4*)&Bs[k][tc * 4];
            acc[0][0] += a.x * bv.x; acc[0][1] += a.x * bv.y; acc[0][2] += a.x * bv.z; acc[0][3] += a.x * bv.w;
            acc[1][0] += a.y * bv.x; acc[1][1] += a.y * bv.y; acc[1][2] += a.y * bv.z; acc[1][3] += a.y * bv.w;
            acc[2][0] += a.z * bv.x; acc[2][1] += a.z * bv.y; acc[2][2] += a.z * bv.z; acc[2][3] += a.z * bv.w;
            acc[3][0] += a.w * bv.x; acc[3][1] += a.w * bv.y; acc[3][2] += a.w * bv.z; acc[3][3] += a.w * bv.w;
        }
        __syncthreads();
    }
#pragma unroll
    for (int i = 0; i < 4; i++) {
        int m = m0 + tr * 4 + i;
#pragma unroll
        for (int j = 0; j < 4; j++) {
            int n = n0 + tc * 4 + j;
            float v = acc[i][j] + bias[n];
            if (RELU) v = v > 0.f ? v : 0.f;
            C[(size_t)m * N + n] = v;
        }
    }
}

// ---------------- fused sparse score GEMM ----------------
// Compact rows r: score[r] = sum_a relu(enc_r . Wenc[:,a] + benc[a] + dec[rowb[r],a]) * wfull[a] + bfull
__global__ void k_scores(const float* __restrict__ Wenc, const float* __restrict__ benc,
                         const float* __restrict__ wfull, const float* __restrict__ bfull) {
    int R = g_R;
    int r0 = blockIdx.x * 64;
    if (r0 >= R) return;

    __shared__ float As[64][64];   // [k][row]
    __shared__ float Bs[64][64];   // [k][col]
    __shared__ int   rb[64];
    __shared__ float ws[64], bes[64];
    __shared__ float red[64][17];

    int tid = threadIdx.x;  // 256
    for (int t = tid; t < 4096; t += 256) {
        int m = t >> 6, k = t & 63;
        float v = 0.f;
        if (r0 + m < R) v = g_encR[(size_t)(r0 + m) * 64 + k];
        As[k][m] = v;
    }
    if (tid < 64) rb[tid] = (r0 + tid < R) ? g_rowb[r0 + tid] : 0;

    int tr = tid >> 4, tc = tid & 15;
    float rowsum[4] = {0.f, 0.f, 0.f, 0.f};

    for (int ct = 0; ct < 16; ct++) {
        int n0 = ct * 64;
        __syncthreads();
        for (int t = tid; t < 1024; t += 256) {   // 1024 float4 slots? no: t indexes float4
            int k = t >> 4, c = (t & 15) << 2;
            *(float4*)&Bs[k][c] = *(const float4*)(Wenc + (size_t)k * 1024 + n0 + c);
        }
        if (tid < 64) { ws[tid] = wfull[n0 + tid]; bes[tid] = benc[n0 + tid]; }
        __syncthreads();

        float acc[4][4] = {};
#pragma unroll 8
        for (int k = 0; k < 64; k++) {
            float4 a  = *(float4*)&As[k][tr * 4];
            float4 bv = *(float4*)&Bs[k][tc * 4];
            acc[0][0] += a.x * bv.x; acc[0][1] += a.x * bv.y; acc[0][2] += a.x * bv.z; acc[0][3] += a.x * bv.w;
            acc[1][0] += a.y * bv.x; acc[1][1] += a.y * bv.y; acc[1][2] += a.y * bv.z; acc[1][3] += a.y * bv.w;
            acc[2][0] += a.z * bv.x; acc[2][1] += a.z * bv.y; acc[2][2] += a.z * bv.z; acc[2][3] += a.z * bv.w;
            acc[3][0] += a.w * bv.x; acc[3][1] += a.w * bv.y; acc[3][2] += a.w * bv.z; acc[3][3] += a.w * bv.w;
        }
#pragma unroll
        for (int i = 0; i < 4; i++) {
            int brow = rb[tr * 4 + i];
            const float* decrow = g_dec + (size_t)brow * 1024 + n0;
#pragma unroll
            for (int j = 0; j < 4; j++) {
                int c = tc * 4 + j;
                float v = acc[i][j] + bes[c] + decrow[c];
                v = v > 0.f ? v : 0.f;
                rowsum[i] += v * ws[c];
            }
        }
    }
#pragma unroll
    for (int i = 0; i < 4; i++) red[tr * 4 + i][tc] = rowsum[i];
    __syncthreads();
    if (tid < 64) {
        float ssum = 0.f;
#pragma unroll
        for (int c = 0; c < 16; c++) ssum += red[tid][c];
        if (r0 + tid < R) g_scoreR[r0 + tid] = ssum + bfull[0];
    }
}

// ---------------- softmax + ctx + embed, per anchor ----------------
__global__ void k_softctx(const float* __restrict__ benc, const float* __restrict__ wfull,
                          const float* __restrict__ bfull, const float* __restrict__ end_pos,
                          const float* __restrict__ rel_pos, const float* __restrict__ Wemb,
                          const float* __restrict__ bemb) {
    int b = blockIdx.x;
    int tid = threadIdx.x;  // 128
    __shared__ float red[128];
    __shared__ float sc[64];
    __shared__ float alpha[64];

    int base = g_base[b], nnz = g_nnz[b];

    // empty-cell score: relu(benc + dec[b]) . wfull
    float p = 0.f;
    for (int a = tid; a < 1024; a += 128) {
        float v = benc[a] + g_dec[(size_t)b * 1024 + a];
        if (v > 0.f) p += v * wfull[a];
    }
    red[tid] = p;
    if (tid < nnz) sc[tid] = g_scoreR[base + tid];
    __syncthreads();
    for (int st = 64; st > 0; st >>= 1) {
        if (tid < st) red[tid] += red[tid + st];
        __syncthreads();
    }
    if (tid == 0) {
        float se = red[0] + bfull[0];
        float m = se;
        for (int t = 0; t < nnz; t++) m = fmaxf(m, sc[t]);
        float Z = (float)(64 - nnz) * expf(se - m);
        for (int t = 0; t < nnz; t++) { float e = expf(sc[t] - m); alpha[t] = e; Z += e; }
        float inv = 1.0f / Z;
        for (int t = 0; t < nnz; t++) alpha[t] *= inv;
    }
    __syncthreads();

    if (tid < 64) {
        float c = 0.f;
        for (int t = 0; t < nnz; t++) c += alpha[t] * g_encR[(size_t)(base + t) * 64 + tid];
        g_ctxemb[b * PADK + tid] = c;
    } else if (tid < 68) {
        int j = tid - 64;
        float v = end_pos[b * 2 + 0] * Wemb[0 * 4 + j] + end_pos[b * 2 + 1] * Wemb[1 * 4 + j]
                + rel_pos[b * 2 + 0] * Wemb[2 * 4 + j] + rel_pos[b * 2 + 1] * Wemb[3 * 4 + j]
                + bemb[j];
        g_ctxemb[b * PADK + tid] = v > 0.f ? v : 0.f;
    } else if (tid < PADK) {
        g_ctxemb[b * PADK + tid] = 0.f;
    }
}

// ---------------- pad W_out (68 -> 80 rows) ----------------
__global__ void k_padW(const float* __restrict__ Wout) {
    int idx = blockIdx.x * blockDim.x + threadIdx.x;
    if (idx < PADK * ATTD) {
        int k = idx >> 10;
        g_WoutP[idx] = (k < 68) ? Wout[idx] : 0.f;
    }
}

// ---------------- batchnorm stats over rows (axis 0) ----------------
__global__ void k_bnstats(const float* __restrict__ gamma, const float* __restrict__ beta) {
    int c0 = blockIdx.x * 64;
    int c = threadIdx.x & 63;
    int rg = threadIdx.x >> 6;   // 0..3
    float s = 0.f, s2 = 0.f;
    for (int r = rg; r < BQ; r += 4) {
        float v = g_x[(size_t)r * ATTD + c0 + c];
        s += v; s2 += v * v;
    }
    __shared__ float ss[4][64], ss2[4][64];
    ss[rg][c] = s; ss2[rg][c] = s2;
    __syncthreads();
    if (rg == 0) {
        float t  = ss[0][c] + ss[1][c] + ss[2][c] + ss[3][c];
        float t2 = ss2[0][c] + ss2[1][c] + ss2[2][c] + ss2[3][c];
        float mu = t / (float)BQ;
        float var = t2 / (float)BQ - mu * mu;
        float rstd = rsqrtf(var + 1e-5f);
        float ga = gamma[c0 + c] * rstd;
        g_bna[c0 + c] = ga;
        g_bnb[c0 + c] = beta[c0 + c] - mu * ga;
    }
}

__global__ void k_bnapply(float* __restrict__ out) {
    int idx = blockIdx.x * blockDim.x + threadIdx.x;
    if (idx < BQ * ATTD) {
        int c = idx & 1023;
        float v = g_x[idx] * g_bna[c] + g_bnb[c];
        out[idx] = v > 0.f ? v : 0.f;
    }
}

// ---------------- launch ----------------
extern "C" void kernel_launch(void* const* d_in, const int* in_sizes, int n_in,
                              void* d_out, int out_size) {
    const float* h       = (const float*)d_in[0];
    // d_in[1] = seq_start_end (unused, uniform bounds)
    const float* end_pos = (const float*)d_in[2];
    const float* rel_pos = (const float*)d_in[3];
    const float* Wenc    = (const float*)d_in[4];
    const float* benc    = (const float*)d_in[5];
    const float* Wdec    = (const float*)d_in[6];
    const float* bdec    = (const float*)d_in[7];
    const float* wfull   = (const float*)d_in[8];
    const float* bfull   = (const float*)d_in[9];
    const float* Wemb    = (const float*)d_in[10];
    const float* bemb    = (const float*)d_in[11];
    const float* Wout    = (const float*)d_in[12];
    const float* bout    = (const float*)d_in[13];
    const float* Wmlp    = (const float*)d_in[14];
    const float* bmlp    = (const float*)d_in[15];
    const float* gamma   = (const float*)d_in[16];
    const float* beta    = (const float*)d_in[17];
    float* out = (float*)d_out;

    float *p_dec, *p_ctxemb, *p_WoutP, *p_out, *p_x;
    cudaGetSymbolAddress((void**)&p_dec,    g_dec);
    cudaGetSymbolAddress((void**)&p_ctxemb, g_ctxemb);
    cudaGetSymbolAddress((void**)&p_WoutP,  g_WoutP);
    cudaGetSymbolAddress((void**)&p_out,    g_out);
    cudaGetSymbolAddress((void**)&p_x,      g_x);

    k_init<<<1, 1>>>();
    k_pool<<<BQ, 64>>>(h, end_pos);
    k_sgemm<0><<<dim3(ATTD / 64, BQ / 64), 256>>>(h, Wdec, bdec, p_dec, ATTD, HD);
    k_padW<<<(PADK * ATTD + 255) / 256, 256>>>(Wout);
    k_scores<<<(BQ * 63 + 63) / 64, 256>>>(Wenc, benc, wfull, bfull);
    k_softctx<<<BQ, 128>>>(benc, wfull, bfull, end_pos, rel_pos, Wemb, bemb);
    k_sgemm<1><<<dim3(ATTD / 64, BQ / 64), 256>>>(p_ctxemb, p_WoutP, bout, p_out, ATTD, PADK);
    k_sgemm<0><<<dim3(ATTD / 64, BQ / 64), 256>>>(p_out, Wmlp, bmlp, p_x, ATTD, ATTD);
    k_bnstats<<<ATTD / 64, 256>>>(gamma, beta);
    k_bnapply<<<(BQ * ATTD + 255) / 256, 256>>>(out);
}

// round 2
// speedup vs baseline: 1.2308x; 1.2308x over previous
#include <cuda_runtime.h>
#include <math.h>

#define BQ   2048     // total agents (B)
#define HD   64
#define ATTD 1024
#define PADK 80       // 68 padded to multiple of 16

typedef unsigned long long ull;

// ---------------- packed f32x2 helpers (FFMA2 path, not emitted by ptxas) ----
__device__ __forceinline__ void ffma2(ull& d, ull a, ull b) {
    asm("fma.rn.f32x2 %0, %1, %2, %0;" : "+l"(d) : "l"(a), "l"(b));
}
__device__ __forceinline__ ull f2rep(float x) {
    ull r; asm("mov.b64 %0, {%1, %1};" : "=l"(r) : "f"(x)); return r;
}
__device__ __forceinline__ float2 f2unpack(ull v) {
    float2 r; asm("mov.b64 {%0, %1}, %2;" : "=f"(r.x), "=f"(r.y) : "l"(v)); return r;
}

// ---------------- device scratch (static, no allocations) ----------------
__device__ float g_dec[BQ * ATTD];                 // dec_a = h@W_dec + b_dec
__device__ float g_encR[(size_t)BQ * 64 * HD];     // compacted nonzero enc rows
__device__ int   g_rowb[BQ * 64];                  // anchor id per compact row
__device__ int   g_base[BQ];                       // compact base per anchor
__device__ int   g_nnz[BQ];                        // nonzero cell count per anchor
__device__ float g_scoreR[BQ * 64];                // score per compact row
__device__ int   g_R;                              // total compact rows
__device__ float g_ctxemb[BQ * PADK];              // [ctx(64) | emb(4) | zeros(12)]
__device__ float g_WoutP[PADK * ATTD];             // W_out padded 68->80 rows
__device__ float g_out[BQ * ATTD];
__device__ float g_x[BQ * ATTD];
__device__ float g_bna[ATTD];
__device__ float g_bnb[ATTD];

__global__ void k_init() { g_R = 0; }

// ---------------- social pooling + compaction (block per anchor) ----------------
__global__ void k_pool(const float* __restrict__ h, const float* __restrict__ end_pos) {
    int b = blockIdx.x;
    int s = b >> 6;
    int i = b & 63;
    int d = threadIdx.x;

    __shared__ float hsh[64 * 64];
    __shared__ float acc[64 * 64];
    __shared__ float px[64], py[64];
    __shared__ int   cellj[64];
    __shared__ int   nz[64];
    __shared__ int   slot_cell[64];
    __shared__ int   sh_base, sh_n;

    for (int t = d; t < 4096; t += 64) { hsh[t] = h[s * 4096 + t]; acc[t] = 0.f; }
    px[d] = end_pos[(s * 64 + d) * 2 + 0];
    py[d] = end_pos[(s * 64 + d) * 2 + 1];
    nz[d] = 0;
    __syncthreads();

    {
        float ax = px[i], ay = py[i];
        float tlx = ax - 1.0f, tly = ay + 1.0f;
        float brx = ax + 1.0f, bry = ay - 1.0f;
        float ox = px[d], oy = py[d];
        bool oob = (ox >= brx) || (ox <= tlx) || (oy >= tly) || (oy <= bry) || (d == i);
        int c = -1;
        if (!oob) {
            float cx = floorf((ox - tlx) / 2.0f * 8.0f);
            float cy = floorf((tly - oy) / 2.0f * 8.0f);
            c = (int)(cx + cy * 8.0f);
        }
        cellj[d] = c;
    }
    __syncthreads();

    for (int j = 0; j < 64; j++) {
        int c = cellj[j];
        if (c >= 0) {
            acc[c * 64 + d] += hsh[j * 64 + d];
            nz[c] = 1;
        }
    }
    __syncthreads();

    if (d == 0) {
        int n = 0;
        for (int c = 0; c < 64; c++) if (nz[c]) slot_cell[n++] = c;
        int base = atomicAdd(&g_R, n);
        sh_base = base; sh_n = n;
        g_base[b] = base; g_nnz[b] = n;
    }
    __syncthreads();

    int base = sh_base, n = sh_n;
    for (int t = 0; t < n; t++) {
        int c = slot_cell[t];
        g_encR[(size_t)(base + t) * 64 + d] = acc[c * 64 + d];
        if (d == 0) g_rowb[base + t] = b;
    }
}

// ---------------- fp32x2 SGEMM: C = act(A[M,K]@B[K,N] + bias) -----------------
// 128x128 block tile, 256 threads, 8x8 micro (split 4+4), packed FFMA2.
// Requires: grid covers M,N exactly (multiples of 128); K multiple of 16.
template<int RELU>
__global__ void __launch_bounds__(256) k_sgemm(const float* __restrict__ A,
                                               const float* __restrict__ B,
                                               const float* __restrict__ bias,
                                               float* __restrict__ C,
                                               int N, int K) {
    __shared__ __align__(16) float As[16][128];
    __shared__ __align__(16) float Bs[16][128];
    int tid = threadIdx.x;
    int m0 = blockIdx.y * 128;
    int n0 = blockIdx.x * 128;
    int tr = tid >> 4, tc = tid & 15;

    int la_row = tid >> 1;          // 0..127
    int la_k   = (tid & 1) * 8;     // 0 or 8
    int lb_k   = tid >> 4;          // 0..15
    int lb_c   = (tid & 15) * 8;    // 0..120

    ull acc[8][4];
#pragma unroll
    for (int i = 0; i < 8; i++)
#pragma unroll
        for (int j = 0; j < 4; j++) acc[i][j] = 0ull;

    for (int k0 = 0; k0 < K; k0 += 16) {
        float4 av0 = *(const float4*)(A + (size_t)(m0 + la_row) * K + k0 + la_k);
        float4 av1 = *(const float4*)(A + (size_t)(m0 + la_row) * K + k0 + la_k + 4);
        As[la_k + 0][la_row] = av0.x; As[la_k + 1][la_row] = av0.y;
        As[la_k + 2][la_row] = av0.z; As[la_k + 3][la_row] = av0.w;
        As[la_k + 4][la_row] = av1.x; As[la_k + 5][la_row] = av1.y;
        As[la_k + 6][la_row] = av1.z; As[la_k + 7][la_row] = av1.w;
        *(float4*)&Bs[lb_k][lb_c]     = *(const float4*)(B + (size_t)(k0 + lb_k) * N + n0 + lb_c);
        *(float4*)&Bs[lb_k][lb_c + 4] = *(const float4*)(B + (size_t)(k0 + lb_k) * N + n0 + lb_c + 4);
        __syncthreads();
#pragma unroll
        for (int k = 0; k < 16; k++) {
            float4 a0 = *(float4*)&As[k][tr * 4];
            float4 a1 = *(float4*)&As[k][64 + tr * 4];
            ulonglong2 b0 = *(ulonglong2*)&Bs[k][tc * 4];
            ulonglong2 b1 = *(ulonglong2*)&Bs[k][64 + tc * 4];
            ull ap;
            ap = f2rep(a0.x); ffma2(acc[0][0], ap, b0.x); ffma2(acc[0][1], ap, b0.y); ffma2(acc[0][2], ap, b1.x); ffma2(acc[0][3], ap, b1.y);
            ap = f2rep(a0.y); ffma2(acc[1][0], ap, b0.x); ffma2(acc[1][1], ap, b0.y); ffma2(acc[1][2], ap, b1.x); ffma2(acc[1][3], ap, b1.y);
            ap = f2rep(a0.z); ffma2(acc[2][0], ap, b0.x); ffma2(acc[2][1], ap, b0.y); ffma2(acc[2][2], ap, b1.x); ffma2(acc[2][3], ap, b1.y);
            ap = f2rep(a0.w); ffma2(acc[3][0], ap, b0.x); ffma2(acc[3][1], ap, b0.y); ffma2(acc[3][2], ap, b1.x); ffma2(acc[3][3], ap, b1.y);
            ap = f2rep(a1.x); ffma2(acc[4][0], ap, b0.x); ffma2(acc[4][1], ap, b0.y); ffma2(acc[4][2], ap, b1.x); ffma2(acc[4][3], ap, b1.y);
            ap = f2rep(a1.y); ffma2(acc[5][0], ap, b0.x); ffma2(acc[5][1], ap, b0.y); ffma2(acc[5][2], ap, b1.x); ffma2(acc[5][3], ap, b1.y);
            ap = f2rep(a1.z); ffma2(acc[6][0], ap, b0.x); ffma2(acc[6][1], ap, b0.y); ffma2(acc[6][2], ap, b1.x); ffma2(acc[6][3], ap, b1.y);
            ap = f2rep(a1.w); ffma2(acc[7][0], ap, b0.x); ffma2(acc[7][1], ap, b0.y); ffma2(acc[7][2], ap, b1.x); ffma2(acc[7][3], ap, b1.y);
        }
        __syncthreads();
    }

    float4 bv0 = *(const float4*)(bias + n0 + tc * 4);
    float4 bv1 = *(const float4*)(bias + n0 + 64 + tc * 4);
#pragma unroll
    for (int i = 0; i < 8; i++) {
        int m = m0 + ((i < 4) ? (tr * 4 + i) : (64 + tr * 4 + i - 4));
        float2 p0 = f2unpack(acc[i][0]);
        float2 p1 = f2unpack(acc[i][1]);
        float2 p2 = f2unpack(acc[i][2]);
        float2 p3 = f2unpack(acc[i][3]);
        float4 o0 = make_float4(p0.x + bv0.x, p0.y + bv0.y, p1.x + bv0.z, p1.y + bv0.w);
        float4 o1 = make_float4(p2.x + bv1.x, p2.y + bv1.y, p3.x + bv1.z, p3.y + bv1.w);
        if (RELU) {
            o0.x = fmaxf(o0.x, 0.f); o0.y = fmaxf(o0.y, 0.f); o0.z = fmaxf(o0.z, 0.f); o0.w = fmaxf(o0.w, 0.f);
            o1.x = fmaxf(o1.x, 0.f); o1.y = fmaxf(o1.y, 0.f); o1.z = fmaxf(o1.z, 0.f); o1.w = fmaxf(o1.w, 0.f);
        }
        *(float4*)(C + (size_t)m * N + n0 + tc * 4)      = o0;
        *(float4*)(C + (size_t)m * N + n0 + 64 + tc * 4) = o1;
    }
}

// ---------------- fused sparse score GEMM (packed f32x2) ----------------
// Compact rows r: score[r] = sum_a relu(enc_r . Wenc[:,a] + benc[a] + dec[rowb[r],a]) * wfull[a] + bfull
// 64-row tile x 128-col tiles, K=64 A-tile resident in smem, 4x8 micro.
__global__ void __launch_bounds__(256) k_scores(const float* __restrict__ Wenc,
                                                const float* __restrict__ benc,
                                                const float* __restrict__ wfull,
                                                const float* __restrict__ bfull) {
    int R = g_R;
    int r0 = blockIdx.x * 64;
    if (r0 >= R) return;

    __shared__ __align__(16) float As[64][68];   // [k][row], pad keeps 16B align
    __shared__ __align__(16) float Bs[16][128];
    __shared__ int   rb[64];
    __shared__ float ws[128], bes[128];
    __shared__ float red[64][17];

    int tid = threadIdx.x;  // 256
    int tr = tid >> 4, tc = tid & 15;

    // load + transpose A tile (64 rows x 64 k), zero-pad rows >= R
#pragma unroll
    for (int it = 0; it < 4; it++) {
        int t = tid + it * 256;           // 0..1023
        int row = t >> 4;
        int kq = (t & 15) * 4;
        float4 v = make_float4(0.f, 0.f, 0.f, 0.f);
        if (r0 + row < R) v = *(const float4*)(g_encR + (size_t)(r0 + row) * 64 + kq);
        As[kq + 0][row] = v.x; As[kq + 1][row] = v.y;
        As[kq + 2][row] = v.z; As[kq + 3][row] = v.w;
    }
    if (tid < 64) rb[tid] = (r0 + tid < R) ? g_rowb[r0 + tid] : 0;

    int lb_k = tid >> 4;          // 0..15
    int lb_c = (tid & 15) * 8;    // 0..120

    float rowsum[4] = {0.f, 0.f, 0.f, 0.f};

    for (int ct = 0; ct < 8; ct++) {
        int n0 = ct * 128;
        __syncthreads();                     // protect ws/bes vs prior epilogue
        if (tid < 128) { ws[tid] = wfull[n0 + tid]; bes[tid] = benc[n0 + tid]; }

        ull acc[4][4];
#pragma unroll
        for (int i = 0; i < 4; i++)
#pragma unroll
            for (int j = 0; j < 4; j++) acc[i][j] = 0ull;

        for (int ks = 0; ks < 4; ks++) {
            __syncthreads();                 // Bs consumers done
            *(float4*)&Bs[lb_k][lb_c]     = *(const float4*)(Wenc + (size_t)(ks * 16 + lb_k) * 1024 + n0 + lb_c);
            *(float4*)&Bs[lb_k][lb_c + 4] = *(const float4*)(Wenc + (size_t)(ks * 16 + lb_k) * 1024 + n0 + lb_c + 4);
            __syncthreads();
#pragma unroll
            for (int k = 0; k < 16; k++) {
                int kk = ks * 16 + k;
                float4 a = *(float4*)&As[kk][tr * 4];
                ulonglong2 b0 = *(ulonglong2*)&Bs[k][tc * 4];
                ulonglong2 b1 = *(ulonglong2*)&Bs[k][64 + tc * 4];
                ull ap;
                ap = f2rep(a.x); ffma2(acc[0][0], ap, b0.x); ffma2(acc[0][1], ap, b0.y); ffma2(acc[0][2], ap, b1.x); ffma2(acc[0][3], ap, b1.y);
                ap = f2rep(a.y); ffma2(acc[1][0], ap, b0.x); ffma2(acc[1][1], ap, b0.y); ffma2(acc[1][2], ap, b1.x); ffma2(acc[1][3], ap, b1.y);
                ap = f2rep(a.z); ffma2(acc[2][0], ap, b0.x); ffma2(acc[2][1], ap, b0.y); ffma2(acc[2][2], ap, b1.x); ffma2(acc[2][3], ap, b1.y);
                ap = f2rep(a.w); ffma2(acc[3][0], ap, b0.x); ffma2(acc[3][1], ap, b0.y); ffma2(acc[3][2], ap, b1.x); ffma2(acc[3][3], ap, b1.y);
            }
        }

        // epilogue for this column tile: relu(acc + benc + dec) . wfull
#pragma unroll
        for (int i = 0; i < 4; i++) {
            int brow = rb[tr * 4 + i];
            const float* decrow = g_dec + (size_t)brow * 1024 + n0;
            float4 d0 = *(const float4*)(decrow + tc * 4);
            float4 d1 = *(const float4*)(decrow + 64 + tc * 4);
            float2 p0 = f2unpack(acc[i][0]);
            float2 p1 = f2unpack(acc[i][1]);
            float2 p2 = f2unpack(acc[i][2]);
            float2 p3 = f2unpack(acc[i][3]);
            int c0 = tc * 4, c1 = 64 + tc * 4;
            float v;
            v = p0.x + bes[c0 + 0] + d0.x; if (v > 0.f) rowsum[i] += v * ws[c0 + 0];
            v = p0.y + bes[c0 + 1] + d0.y; if (v > 0.f) rowsum[i] += v * ws[c0 + 1];
            v = p1.x + bes[c0 + 2] + d0.z; if (v > 0.f) rowsum[i] += v * ws[c0 + 2];
            v = p1.y + bes[c0 + 3] + d0.w; if (v > 0.f) rowsum[i] += v * ws[c0 + 3];
            v = p2.x + bes[c1 + 0] + d1.x; if (v > 0.f) rowsum[i] += v * ws[c1 + 0];
            v = p2.y + bes[c1 + 1] + d1.y; if (v > 0.f) rowsum[i] += v * ws[c1 + 1];
            v = p3.x + bes[c1 + 2] + d1.z; if (v > 0.f) rowsum[i] += v * ws[c1 + 2];
            v = p3.y + bes[c1 + 3] + d1.w; if (v > 0.f) rowsum[i] += v * ws[c1 + 3];
        }
    }

#pragma unroll
    for (int i = 0; i < 4; i++) red[tr * 4 + i][tc] = rowsum[i];
    __syncthreads();
    if (tid < 64) {
        float ssum = 0.f;
#pragma unroll
        for (int c = 0; c < 16; c++) ssum += red[tid][c];
        if (r0 + tid < R) g_scoreR[r0 + tid] = ssum + bfull[0];
    }
}

// ---------------- softmax + ctx + embed, per anchor ----------------
__global__ void k_softctx(const float* __restrict__ benc, const float* __restrict__ wfull,
                          const float* __restrict__ bfull, const float* __restrict__ end_pos,
                          const float* __restrict__ rel_pos, const float* __restrict__ Wemb,
                          const float* __restrict__ bemb) {
    int b = blockIdx.x;
    int tid = threadIdx.x;  // 128
    __shared__ float red[128];
    __shared__ float sc[64];
    __shared__ float alpha[64];

    int base = g_base[b], nnz = g_nnz[b];

    float p = 0.f;
    for (int a = tid; a < 1024; a += 128) {
        float v = benc[a] + g_dec[(size_t)b * 1024 + a];
        if (v > 0.f) p += v * wfull[a];
    }
    red[tid] = p;
    if (tid < nnz) sc[tid] = g_scoreR[base + tid];
    __syncthreads();
    for (int st = 64; st > 0; st >>= 1) {
        if (tid < st) red[tid] += red[tid + st];
        __syncthreads();
    }
    if (tid == 0) {
        float se = red[0] + bfull[0];
        float m = se;
        for (int t = 0; t < nnz; t++) m = fmaxf(m, sc[t]);
        float Z = (float)(64 - nnz) * expf(se - m);
        for (int t = 0; t < nnz; t++) { float e = expf(sc[t] - m); alpha[t] = e; Z += e; }
        float inv = 1.0f / Z;
        for (int t = 0; t < nnz; t++) alpha[t] *= inv;
    }
    __syncthreads();

    if (tid < 64) {
        float c = 0.f;
        for (int t = 0; t < nnz; t++) c += alpha[t] * g_encR[(size_t)(base + t) * 64 + tid];
        g_ctxemb[b * PADK + tid] = c;
    } else if (tid < 68) {
        int j = tid - 64;
        float v = end_pos[b * 2 + 0] * Wemb[0 * 4 + j] + end_pos[b * 2 + 1] * Wemb[1 * 4 + j]
                + rel_pos[b * 2 + 0] * Wemb[2 * 4 + j] + rel_pos[b * 2 + 1] * Wemb[3 * 4 + j]
                + bemb[j];
        g_ctxemb[b * PADK + tid] = v > 0.f ? v : 0.f;
    } else if (tid < PADK) {
        g_ctxemb[b * PADK + tid] = 0.f;
    }
}

// ---------------- pad W_out (68 -> 80 rows) ----------------
__global__ void k_padW(const float* __restrict__ Wout) {
    int idx = blockIdx.x * blockDim.x + threadIdx.x;
    if (idx < PADK * ATTD) {
        int k = idx >> 10;
        g_WoutP[idx] = (k < 68) ? Wout[idx] : 0.f;
    }
}

// ---------------- batchnorm stats over rows (axis 0) ----------------
__global__ void k_bnstats(const float* __restrict__ gamma, const float* __restrict__ beta) {
    int c0 = blockIdx.x * 64;
    int c = threadIdx.x & 63;
    int rg = threadIdx.x >> 6;   // 0..3
    float s = 0.f, s2 = 0.f;
    for (int r = rg; r < BQ; r += 4) {
        float v = g_x[(size_t)r * ATTD + c0 + c];
        s += v; s2 += v * v;
    }
    __shared__ float ss[4][64], ss2[4][64];
    ss[rg][c] = s; ss2[rg][c] = s2;
    __syncthreads();
    if (rg == 0) {
        float t  = ss[0][c] + ss[1][c] + ss[2][c] + ss[3][c];
        float t2 = ss2[0][c] + ss2[1][c] + ss2[2][c] + ss2[3][c];
        float mu = t / (float)BQ;
        float var = t2 / (float)BQ - mu * mu;
        float rstd = rsqrtf(var + 1e-5f);
        float ga = gamma[c0 + c] * rstd;
        g_bna[c0 + c] = ga;
        g_bnb[c0 + c] = beta[c0 + c] - mu * ga;
    }
}

__global__ void k_bnapply(float* __restrict__ out) {
    int idx = blockIdx.x * blockDim.x + threadIdx.x;
    if (idx < BQ * ATTD) {
        int c = idx & 1023;
        float v = g_x[idx] * g_bna[c] + g_bnb[c];
        out[idx] = v > 0.f ? v : 0.f;
    }
}

// ---------------- launch ----------------
extern "C" void kernel_launch(void* const* d_in, const int* in_sizes, int n_in,
                              void* d_out, int out_size) {
    const float* h       = (const float*)d_in[0];
    const float* end_pos = (const float*)d_in[2];
    const float* rel_pos = (const float*)d_in[3];
    const float* Wenc    = (const float*)d_in[4];
    const float* benc    = (const float*)d_in[5];
    const float* Wdec    = (const float*)d_in[6];
    const float* bdec    = (const float*)d_in[7];
    const float* wfull   = (const float*)d_in[8];
    const float* bfull   = (const float*)d_in[9];
    const float* Wemb    = (const float*)d_in[10];
    const float* bemb    = (const float*)d_in[11];
    const float* Wout    = (const float*)d_in[12];
    const float* bout    = (const float*)d_in[13];
    const float* Wmlp    = (const float*)d_in[14];
    const float* bmlp    = (const float*)d_in[15];
    const float* gamma   = (const float*)d_in[16];
    const float* beta    = (const float*)d_in[17];
    float* out = (float*)d_out;

    float *p_dec, *p_ctxemb, *p_WoutP, *p_out, *p_x;
    cudaGetSymbolAddress((void**)&p_dec,    g_dec);
    cudaGetSymbolAddress((void**)&p_ctxemb, g_ctxemb);
    cudaGetSymbolAddress((void**)&p_WoutP,  g_WoutP);
    cudaGetSymbolAddress((void**)&p_out,    g_out);
    cudaGetSymbolAddress((void**)&p_x,      g_x);

    dim3 gg(ATTD / 128, BQ / 128);   // (8, 16) = 128 blocks

    k_init<<<1, 1>>>();
    k_pool<<<BQ, 64>>>(h, end_pos);
    k_sgemm<0><<<gg, 256>>>(h, Wdec, bdec, p_dec, ATTD, HD);
    k_padW<<<(PADK * ATTD + 255) / 256, 256>>>(Wout);
    k_scores<<<BQ * 64 / 64, 256>>>(Wenc, benc, wfull, bfull);
    k_softctx<<<BQ, 128>>>(benc, wfull, bfull, end_pos, rel_pos, Wemb, bemb);
    k_sgemm<1><<<gg, 256>>>(p_ctxemb, p_WoutP, bout, p_out, ATTD, PADK);
    k_sgemm<0><<<gg, 256>>>(p_out, Wmlp, bmlp, p_x, ATTD, ATTD);
    k_bnstats<<<ATTD / 64, 256>>>(gamma, beta);
    k_bnapply<<<(BQ * ATTD + 255) / 256, 256>>>(out);
}

// round 3
// speedup vs baseline: 1.4445x; 1.1736x over previous
#include <cuda_runtime.h>
#include <math.h>

#define BQ   2048     // total agents (B)
#define HD   64
#define ATTD 1024
#define PADK 80       // 68 padded to multiple of 16

typedef unsigned long long ull;

// ---------------- packed f32x2 helpers ----------------
__device__ __forceinline__ void ffma2(ull& d, ull a, ull b) {
    asm("fma.rn.f32x2 %0, %1, %2, %0;" : "+l"(d) : "l"(a), "l"(b));
}
__device__ __forceinline__ ull f2rep(float x) {
    ull r; asm("mov.b64 %0, {%1, %1};" : "=l"(r) : "f"(x)); return r;
}
__device__ __forceinline__ float2 f2unpack(ull v) {
    float2 r; asm("mov.b64 {%0, %1}, %2;" : "=f"(r.x), "=f"(r.y) : "l"(v)); return r;
}
// ---------------- cp.async helpers ----------------
__device__ __forceinline__ void cpasync16(void* smem, const void* g) {
    unsigned sa = (unsigned)__cvta_generic_to_shared(smem);
    asm volatile("cp.async.cg.shared.global [%0], [%1], 16;" :: "r"(sa), "l"(g));
}
__device__ __forceinline__ void cp_commit() { asm volatile("cp.async.commit_group;"); }
__device__ __forceinline__ void cp_wait0()  { asm volatile("cp.async.wait_group 0;"); }

// ---------------- device scratch ----------------
__device__ float g_dec[BQ * ATTD];
__device__ float g_encR[(size_t)BQ * 64 * HD];
__device__ int   g_rowb[BQ * 64];
__device__ int   g_base[BQ];
__device__ int   g_nnz[BQ];
__device__ float g_scoreR[BQ * 64];
__device__ int   g_R;
__device__ float g_ctxemb[BQ * PADK];
__device__ float g_WoutP[PADK * ATTD];
__device__ float g_out[BQ * ATTD];
__device__ float g_x[BQ * ATTD];
__device__ float g_bnsum[ATTD];
__device__ float g_bnsum2[ATTD];
__device__ float g_bna[ATTD];
__device__ float g_bnb[ATTD];

// ---------------- prep: pad W_out + zero counters ----------------
__global__ void k_prep(const float* __restrict__ Wout) {
    int idx = blockIdx.x * blockDim.x + threadIdx.x;
    if (idx < PADK * ATTD) g_WoutP[idx] = ((idx >> 10) < 68) ? Wout[idx] : 0.f;
    if (idx < ATTD) { g_bnsum[idx] = 0.f; g_bnsum2[idx] = 0.f; }
    if (idx == 0) g_R = 0;
}

// ---------------- social pooling + compaction ----------------
__global__ void k_pool(const float* __restrict__ h, const float* __restrict__ end_pos) {
    int b = blockIdx.x;
    int s = b >> 6;
    int i = b & 63;
    int d = threadIdx.x;

    __shared__ __align__(16) float hsh[64 * 64];
    __shared__ __align__(16) float acc[64 * 64];
    __shared__ float px[64], py[64];
    __shared__ int   cellj[64];
    __shared__ int   nz[64];
    __shared__ int   slot_cell[64];
    __shared__ int   sh_base, sh_n;

    float4 z4 = make_float4(0.f, 0.f, 0.f, 0.f);
    for (int t = d; t < 1024; t += 64) {
        *(float4*)&hsh[t * 4] = *(const float4*)(h + (size_t)s * 4096 + t * 4);
        *(float4*)&acc[t * 4] = z4;
    }
    px[d] = end_pos[(s * 64 + d) * 2 + 0];
    py[d] = end_pos[(s * 64 + d) * 2 + 1];
    nz[d] = 0;
    __syncthreads();

    {
        float ax = px[i], ay = py[i];
        float tlx = ax - 1.0f, tly = ay + 1.0f;
        float brx = ax + 1.0f, bry = ay - 1.0f;
        float ox = px[d], oy = py[d];
        bool oob = (ox >= brx) || (ox <= tlx) || (oy >= tly) || (oy <= bry) || (d == i);
        int c = -1;
        if (!oob) {
            float cx = floorf((ox - tlx) / 2.0f * 8.0f);
            float cy = floorf((tly - oy) / 2.0f * 8.0f);
            c = (int)(cx + cy * 8.0f);
        }
        cellj[d] = c;
    }
    __syncthreads();

    for (int j = 0; j < 64; j++) {
        int c = cellj[j];
        if (c >= 0) {
            acc[c * 64 + d] += hsh[j * 64 + d];
            nz[c] = 1;
        }
    }
    __syncthreads();

    if (d == 0) {
        int n = 0;
        for (int c = 0; c < 64; c++) if (nz[c]) slot_cell[n++] = c;
        int base = atomicAdd(&g_R, n);
        sh_base = base; sh_n = n;
        g_base[b] = base; g_nnz[b] = n;
    }
    __syncthreads();

    int base = sh_base, n = sh_n;
    for (int t = 0; t < n; t++) {
        int c = slot_cell[t];
        g_encR[(size_t)(base + t) * 64 + d] = acc[c * 64 + d];
        if (d == 0) g_rowb[base + t] = b;
    }
}

// ---------------- pipelined fp32x2 SGEMM: C = act(A@B + bias) ----------------
// 128x128 tile, 256 threads, 2-stage cp.async, 8x8 micro, packed FFMA2.
template<int RELU>
__global__ void __launch_bounds__(256) k_sgemm(const float* __restrict__ A,
                                               const float* __restrict__ B,
                                               const float* __restrict__ bias,
                                               float* __restrict__ C,
                                               int N, int K) {
    __shared__ __align__(16) float As[2][128][16];
    __shared__ __align__(16) float Bs[2][16][128];
    int tid = threadIdx.x;
    int m0 = blockIdx.y * 128;
    int n0 = blockIdx.x * 128;
    int tr = tid >> 4, tc = tid & 15;
    int KT = K >> 4;

    // stage loader: 2 chunks of A + 2 of B per thread
    auto stage_load = [&](int st, int k0) {
#pragma unroll
        for (int q = 0; q < 2; q++) {
            int c = tid + q * 256;           // 0..511
            int ar = c >> 2, ak = (c & 3) * 4;
            cpasync16(&As[st][ar][ak], A + (size_t)(m0 + ar) * K + k0 + ak);
            int bk = c >> 5, bc = (c & 31) * 4;
            cpasync16(&Bs[st][bk][bc], B + (size_t)(k0 + bk) * N + n0 + bc);
        }
    };

    ull acc[8][4];
#pragma unroll
    for (int i = 0; i < 8; i++)
#pragma unroll
        for (int j = 0; j < 4; j++) acc[i][j] = 0ull;

    stage_load(0, 0);
    cp_commit();

    for (int it = 0; it < KT; it++) {
        int cur = it & 1;
        cp_wait0();
        __syncthreads();
        if (it + 1 < KT) stage_load(cur ^ 1, (it + 1) * 16);
        cp_commit();

#pragma unroll
        for (int kg = 0; kg < 4; kg++) {
            float4 ar[8];
#pragma unroll
            for (int i = 0; i < 4; i++) {
                ar[i]     = *(float4*)&As[cur][tr * 4 + i][kg * 4];
                ar[4 + i] = *(float4*)&As[cur][64 + tr * 4 + i][kg * 4];
            }
#pragma unroll
            for (int kk = 0; kk < 4; kk++) {
                int k = kg * 4 + kk;
                ulonglong2 b0 = *(ulonglong2*)&Bs[cur][k][tc * 4];
                ulonglong2 b1 = *(ulonglong2*)&Bs[cur][k][64 + tc * 4];
#pragma unroll
                for (int i = 0; i < 8; i++) {
                    ull ap = f2rep(((const float*)&ar[i])[kk]);
                    ffma2(acc[i][0], ap, b0.x); ffma2(acc[i][1], ap, b0.y);
                    ffma2(acc[i][2], ap, b1.x); ffma2(acc[i][3], ap, b1.y);
                }
            }
        }
        __syncthreads();
    }

    float4 bv0 = *(const float4*)(bias + n0 + tc * 4);
    float4 bv1 = *(const float4*)(bias + n0 + 64 + tc * 4);
#pragma unroll
    for (int i = 0; i < 8; i++) {
        int m = m0 + ((i < 4) ? (tr * 4 + i) : (64 + tr * 4 + i - 4));
        float2 p0 = f2unpack(acc[i][0]);
        float2 p1 = f2unpack(acc[i][1]);
        float2 p2 = f2unpack(acc[i][2]);
        float2 p3 = f2unpack(acc[i][3]);
        float4 o0 = make_float4(p0.x + bv0.x, p0.y + bv0.y, p1.x + bv0.z, p1.y + bv0.w);
        float4 o1 = make_float4(p2.x + bv1.x, p2.y + bv1.y, p3.x + bv1.z, p3.y + bv1.w);
        if (RELU) {
            o0.x = fmaxf(o0.x, 0.f); o0.y = fmaxf(o0.y, 0.f); o0.z = fmaxf(o0.z, 0.f); o0.w = fmaxf(o0.w, 0.f);
            o1.x = fmaxf(o1.x, 0.f); o1.y = fmaxf(o1.y, 0.f); o1.z = fmaxf(o1.z, 0.f); o1.w = fmaxf(o1.w, 0.f);
        }
        *(float4*)(C + (size_t)m * N + n0 + tc * 4)      = o0;
        *(float4*)(C + (size_t)m * N + n0 + 64 + tc * 4) = o1;
    }
}

// ---------------- fused sparse score GEMM (pipelined) ----------------
__global__ void __launch_bounds__(256) k_scores(const float* __restrict__ Wenc,
                                                const float* __restrict__ benc,
                                                const float* __restrict__ wfull,
                                                const float* __restrict__ bfull) {
    int R = g_R;
    int r0 = blockIdx.x * 64;
    if (r0 >= R) return;

    __shared__ __align__(16) float As[64][68];   // [k][row]
    __shared__ __align__(16) float Bs[2][16][128];
    __shared__ int   rb[64];
    __shared__ float ws[1024], bes[1024];
    __shared__ float red[64][17];

    int tid = threadIdx.x;  // 256
    int tr = tid >> 4, tc = tid & 15;

    // A tile load + transpose (64 rows x 64 k)
#pragma unroll
    for (int it = 0; it < 4; it++) {
        int t = tid + it * 256;
        int row = t >> 4;
        int kq = (t & 15) * 4;
        float4 v = make_float4(0.f, 0.f, 0.f, 0.f);
        if (r0 + row < R) v = *(const float4*)(g_encR + (size_t)(r0 + row) * 64 + kq);
        As[kq + 0][row] = v.x; As[kq + 1][row] = v.y;
        As[kq + 2][row] = v.z; As[kq + 3][row] = v.w;
    }
    if (tid < 64) rb[tid] = (r0 + tid < R) ? g_rowb[r0 + tid] : 0;
    for (int i = tid; i < 1024; i += 256) { ws[i] = wfull[i]; bes[i] = benc[i]; }

    // Wenc streaming: 32 tiles of 16x128 (t = ct*4 + ks)
    auto stage_load = [&](int st, int t) {
#pragma unroll
        for (int q = 0; q < 2; q++) {
            int c = tid + q * 256;
            int kr = c >> 5, cc = (c & 31) * 4;
            cpasync16(&Bs[st][kr][cc],
                      Wenc + (size_t)((t & 3) * 16 + kr) * 1024 + (t >> 2) * 128 + cc);
        }
    };

    float rowsum[4] = {0.f, 0.f, 0.f, 0.f};
    ull acc[4][4];

    stage_load(0, 0);
    cp_commit();

    for (int t = 0; t < 32; t++) {
        int cur = t & 1;
        int ks = t & 3, ct = t >> 2;
        cp_wait0();
        __syncthreads();
        if (t + 1 < 32) stage_load(cur ^ 1, t + 1);
        cp_commit();

        if (ks == 0) {
#pragma unroll
            for (int i = 0; i < 4; i++)
#pragma unroll
                for (int j = 0; j < 4; j++) acc[i][j] = 0ull;
        }

#pragma unroll
        for (int k = 0; k < 16; k++) {
            int kk = ks * 16 + k;
            float4 a = *(float4*)&As[kk][tr * 4];
            ulonglong2 b0 = *(ulonglong2*)&Bs[cur][k][tc * 4];
            ulonglong2 b1 = *(ulonglong2*)&Bs[cur][k][64 + tc * 4];
            ull ap;
            ap = f2rep(a.x); ffma2(acc[0][0], ap, b0.x); ffma2(acc[0][1], ap, b0.y); ffma2(acc[0][2], ap, b1.x); ffma2(acc[0][3], ap, b1.y);
            ap = f2rep(a.y); ffma2(acc[1][0], ap, b0.x); ffma2(acc[1][1], ap, b0.y); ffma2(acc[1][2], ap, b1.x); ffma2(acc[1][3], ap, b1.y);
            ap = f2rep(a.z); ffma2(acc[2][0], ap, b0.x); ffma2(acc[2][1], ap, b0.y); ffma2(acc[2][2], ap, b1.x); ffma2(acc[2][3], ap, b1.y);
            ap = f2rep(a.w); ffma2(acc[3][0], ap, b0.x); ffma2(acc[3][1], ap, b0.y); ffma2(acc[3][2], ap, b1.x); ffma2(acc[3][3], ap, b1.y);
        }

        if (ks == 3) {
            int n0 = ct * 128;
#pragma unroll
            for (int i = 0; i < 4; i++) {
                int brow = rb[tr * 4 + i];
                const float* decrow = g_dec + (size_t)brow * 1024 + n0;
                float4 d0 = *(const float4*)(decrow + tc * 4);
                float4 d1 = *(const float4*)(decrow + 64 + tc * 4);
                float2 p0 = f2unpack(acc[i][0]);
                float2 p1 = f2unpack(acc[i][1]);
                float2 p2 = f2unpack(acc[i][2]);
                float2 p3 = f2unpack(acc[i][3]);
                int c0 = n0 + tc * 4, c1 = n0 + 64 + tc * 4;
                float v;
                v = p0.x + bes[c0 + 0] + d0.x; if (v > 0.f) rowsum[i] += v * ws[c0 + 0];
                v = p0.y + bes[c0 + 1] + d0.y; if (v > 0.f) rowsum[i] += v * ws[c0 + 1];
                v = p1.x + bes[c0 + 2] + d0.z; if (v > 0.f) rowsum[i] += v * ws[c0 + 2];
                v = p1.y + bes[c0 + 3] + d0.w; if (v > 0.f) rowsum[i] += v * ws[c0 + 3];
                v = p2.x + bes[c1 + 0] + d1.x; if (v > 0.f) rowsum[i] += v * ws[c1 + 0];
                v = p2.y + bes[c1 + 1] + d1.y; if (v > 0.f) rowsum[i] += v * ws[c1 + 1];
                v = p3.x + bes[c1 + 2] + d1.z; if (v > 0.f) rowsum[i] += v * ws[c1 + 2];
                v = p3.y + bes[c1 + 3] + d1.w; if (v > 0.f) rowsum[i] += v * ws[c1 + 3];
            }
        }
    }

#pragma unroll
    for (int i = 0; i < 4; i++) red[tr * 4 + i][tc] = rowsum[i];
    __syncthreads();
    if (tid < 64) {
        float ssum = 0.f;
#pragma unroll
        for (int c = 0; c < 16; c++) ssum += red[tid][c];
        if (r0 + tid < R) g_scoreR[r0 + tid] = ssum + bfull[0];
    }
}

// ---------------- softmax + ctx + embed ----------------
__global__ void k_softctx(const float* __restrict__ benc, const float* __restrict__ wfull,
                          const float* __restrict__ bfull, const float* __restrict__ end_pos,
                          const float* __restrict__ rel_pos, const float* __restrict__ Wemb,
                          const float* __restrict__ bemb) {
    int b = blockIdx.x;
    int tid = threadIdx.x;  // 128
    __shared__ float red[128];
    __shared__ float sc[64];
    __shared__ float alpha[64];

    int base = g_base[b], nnz = g_nnz[b];

    float p = 0.f;
    for (int a = tid; a < 1024; a += 128) {
        float v = benc[a] + g_dec[(size_t)b * 1024 + a];
        if (v > 0.f) p += v * wfull[a];
    }
    red[tid] = p;
    if (tid < nnz) sc[tid] = g_scoreR[base + tid];
    __syncthreads();
    for (int st = 64; st > 0; st >>= 1) {
        if (tid < st) red[tid] += red[tid + st];
        __syncthreads();
    }
    if (tid == 0) {
        float se = red[0] + bfull[0];
        float m = se;
        for (int t = 0; t < nnz; t++) m = fmaxf(m, sc[t]);
        float Z = (float)(64 - nnz) * expf(se - m);
        for (int t = 0; t < nnz; t++) { float e = expf(sc[t] - m); alpha[t] = e; Z += e; }
        float inv = 1.0f / Z;
        for (int t = 0; t < nnz; t++) alpha[t] *= inv;
    }
    __syncthreads();

    if (tid < 64) {
        float c = 0.f;
        for (int t = 0; t < nnz; t++) c += alpha[t] * g_encR[(size_t)(base + t) * 64 + tid];
        g_ctxemb[b * PADK + tid] = c;
    } else if (tid < 68) {
        int j = tid - 64;
        float v = end_pos[b * 2 + 0] * Wemb[0 * 4 + j] + end_pos[b * 2 + 1] * Wemb[1 * 4 + j]
                + rel_pos[b * 2 + 0] * Wemb[2 * 4 + j] + rel_pos[b * 2 + 1] * Wemb[3 * 4 + j]
                + bemb[j];
        g_ctxemb[b * PADK + tid] = v > 0.f ? v : 0.f;
    } else if (tid < PADK) {
        g_ctxemb[b * PADK + tid] = 0.f;
    }
}

// ---------------- batchnorm: partial sums (128 blocks) + final + apply --------
__global__ void k_bnpart() {
    int bc = blockIdx.x & 15;      // column chunk
    int rs = blockIdx.x >> 4;      // row slice 0..7
    int c = bc * 64 + (threadIdx.x & 63);
    int rg = threadIdx.x >> 6;     // 0..3
    float s = 0.f, s2 = 0.f;
    for (int r = rs * 256 + rg; r < (rs + 1) * 256; r += 4) {
        float v = g_x[(size_t)r * ATTD + c];
        s += v; s2 += v * v;
    }
    __shared__ float ss[4][64], ss2[4][64];
    ss[rg][threadIdx.x & 63] = s; ss2[rg][threadIdx.x & 63] = s2;
    __syncthreads();
    if (rg == 0) {
        int l = threadIdx.x & 63;
        float t  = ss[0][l] + ss[1][l] + ss[2][l] + ss[3][l];
        float t2 = ss2[0][l] + ss2[1][l] + ss2[2][l] + ss2[3][l];
        atomicAdd(&g_bnsum[c], t);
        atomicAdd(&g_bnsum2[c], t2);
    }
}

__global__ void k_bnfinal(const float* __restrict__ gamma, const float* __restrict__ beta) {
    int c = threadIdx.x;
    float mu = g_bnsum[c] / (float)BQ;
    float var = g_bnsum2[c] / (float)BQ - mu * mu;
    float rstd = rsqrtf(var + 1e-5f);
    float ga = gamma[c] * rstd;
    g_bna[c] = ga;
    g_bnb[c] = beta[c] - mu * ga;
}

__global__ void k_bnapply(float* __restrict__ out) {
    int idx = blockIdx.x * blockDim.x + threadIdx.x;
    if (idx < BQ * ATTD) {
        int c = idx & 1023;
        float v = g_x[idx] * g_bna[c] + g_bnb[c];
        out[idx] = v > 0.f ? v : 0.f;
    }
}

// ---------------- launch ----------------
extern "C" void kernel_launch(void* const* d_in, const int* in_sizes, int n_in,
                              void* d_out, int out_size) {
    const float* h       = (const float*)d_in[0];
    const float* end_pos = (const float*)d_in[2];
    const float* rel_pos = (const float*)d_in[3];
    const float* Wenc    = (const float*)d_in[4];
    const float* benc    = (const float*)d_in[5];
    const float* Wdec    = (const float*)d_in[6];
    const float* bdec    = (const float*)d_in[7];
    const float* wfull   = (const float*)d_in[8];
    const float* bfull   = (const float*)d_in[9];
    const float* Wemb    = (const float*)d_in[10];
    const float* bemb    = (const float*)d_in[11];
    const float* Wout    = (const float*)d_in[12];
    const float* bout    = (const float*)d_in[13];
    const float* Wmlp    = (const float*)d_in[14];
    const float* bmlp    = (const float*)d_in[15];
    const float* gamma   = (const float*)d_in[16];
    const float* beta    = (const float*)d_in[17];
    float* out = (float*)d_out;

    float *p_dec, *p_ctxemb, *p_WoutP, *p_out, *p_x;
    cudaGetSymbolAddress((void**)&p_dec,    g_dec);
    cudaGetSymbolAddress((void**)&p_ctxemb, g_ctxemb);
    cudaGetSymbolAddress((void**)&p_WoutP,  g_WoutP);
    cudaGetSymbolAddress((void**)&p_out,    g_out);
    cudaGetSymbolAddress((void**)&p_x,      g_x);

    dim3 gg(ATTD / 128, BQ / 128);   // (8, 16) = 128 blocks

    k_prep<<<(PADK * ATTD + 255) / 256, 256>>>(Wout);
    k_pool<<<BQ, 64>>>(h, end_pos);
    k_sgemm<0><<<gg, 256>>>(h, Wdec, bdec, p_dec, ATTD, HD);
    k_scores<<<BQ, 256>>>(Wenc, benc, wfull, bfull);
    k_softctx<<<BQ, 128>>>(benc, wfull, bfull, end_pos, rel_pos, Wemb, bemb);
    k_sgemm<1><<<gg, 256>>>(p_ctxemb, p_WoutP, bout, p_out, ATTD, PADK);
    k_sgemm<0><<<gg, 256>>>(p_out, Wmlp, bmlp, p_x, ATTD, ATTD);
    k_bnpart<<<128, 256>>>();
    k_bnfinal<<<1, 1024>>>(gamma, beta);
    k_bnapply<<<(BQ * ATTD + 255) / 256, 256>>>(out);
}